// round 3
// baseline (speedup 1.0000x reference)
#include <cuda_runtime.h>
#include <cuda_bf16.h>

#define BSZ   512
#define TT    200
#define HID   128
#define GG    512
#define EMBD  100
#define VOC   30000
#define NCLS  9

__device__ float g_proj[2][VOC * GG];
__device__ float g_h[2][BSZ * TT * HID];

typedef unsigned long long u64;

__device__ __forceinline__ u64 pk2(float lo, float hi) {
    u64 r; asm("mov.b64 %0, {%1,%2};" : "=l"(r) : "f"(lo), "f"(hi)); return r;
}
__device__ __forceinline__ void upk2(u64 v, float& lo, float& hi) {
    asm("mov.b64 {%0,%1}, %2;" : "=f"(lo), "=f"(hi) : "l"(v));
}
__device__ __forceinline__ u64 dup2(float x) { return pk2(x, x); }
__device__ __forceinline__ u64 fma2(u64 a, u64 b, u64 c) {
    u64 d; asm("fma.rn.f32x2 %0, %1, %2, %3;" : "=l"(d) : "l"(a), "l"(b), "l"(c)); return d;
}
__device__ __forceinline__ float sigf(float x) {
    return __fdividef(1.0f, 1.0f + __expf(-x));
}

// ---------------------------------------------------------------------------
// proj[v][j] = sum_e emb[v][e]*W[e][j] + b[j], both directions.
// grid 148 (dir = bid&1, 74 blocks/dir), block 512, thread owns 1 column.
// 16 vocab rows (8 pairs) per tile.
// smem: Wsm[100*512] f32 (204800B) + epack[8*100] f32x2 (6400B)
// ---------------------------------------------------------------------------
__global__ __launch_bounds__(512, 1)
void proj_kernel(const float* __restrict__ emb,
                 const float* __restrict__ Wf, const float* __restrict__ bf,
                 const float* __restrict__ Wb, const float* __restrict__ bb)
{
    extern __shared__ char sm_raw[];
    float* Wsm = (float*)sm_raw;
    u64* epack = (u64*)(sm_raw + 204800);

    const int tid = threadIdx.x;
    const int dir = blockIdx.x & 1;
    const int blk = blockIdx.x >> 1;
    const float* W    = dir ? Wb : Wf;
    const float* bias = dir ? bb : bf;
    float* out = g_proj[dir];
    const int j = tid;

    for (int idx = tid; idx < EMBD * GG; idx += 512) Wsm[idx] = W[idx];
    const float bj = bias[j];
    __syncthreads();

    const int r0 = blk * 406;
    const int r1 = min(r0 + 406, VOC);

    for (int v0 = r0; v0 < r1; v0 += 16) {
        for (int idx = tid; idx < 8 * EMBD; idx += 512) {
            int p = idx / EMBD, k = idx % EMBD;
            int ra = v0 + 2 * p, rb = ra + 1;
            float ea = (ra < VOC) ? emb[ra * EMBD + k] : 0.0f;
            float eb = (rb < VOC) ? emb[rb * EMBD + k] : 0.0f;
            epack[p * EMBD + k] = pk2(ea, eb);
        }
        __syncthreads();

        u64 acc[8];
        #pragma unroll
        for (int p = 0; p < 8; p++) acc[p] = dup2(bj);

        #pragma unroll 5
        for (int k = 0; k < EMBD; k += 2) {
            u64 d0 = dup2(Wsm[k * GG + j]);
            u64 d1 = dup2(Wsm[(k + 1) * GG + j]);
            #pragma unroll
            for (int p = 0; p < 8; p++) {
                ulonglong2 e = *(const ulonglong2*)&epack[p * EMBD + k];
                acc[p] = fma2(e.x, d0, acc[p]);
                acc[p] = fma2(e.y, d1, acc[p]);
            }
        }
        __syncthreads();

        #pragma unroll
        for (int p = 0; p < 8; p++) {
            float oa, ob;
            upk2(acc[p], oa, ob);
            int ra = v0 + 2 * p, rb = ra + 1;
            if (ra < VOC) out[(size_t)ra * GG + j] = oa;
            if (rb < VOC) out[(size_t)rb * GG + j] = ob;
        }
    }
}

// ---------------------------------------------------------------------------
// Persistent recurrent LSTM. grid 128 = 2 dirs x 64 chunks of 8 batch rows.
// block 512; thread owns 1 gate column j = tid, 4 batch row-pairs.
// Epilogue: thread handles hidden m = tid&127, row-pair p = tid>>7.
// smem: Usm[96*512] f32 | hpack[4*128] f32x2 | zex[4*512] f32x2 | tcache[8*200]
// ---------------------------------------------------------------------------
__global__ __launch_bounds__(512, 1)
void lstm_kernel(const int* __restrict__ tokens,
                 const float* __restrict__ Uf, const float* __restrict__ Ub)
{
    extern __shared__ char sm_raw[];
    float* Usm  = (float*)sm_raw;                  // 196608B
    u64* hpack  = (u64*)(sm_raw + 196608);         // 4096B
    u64* zex    = (u64*)(sm_raw + 200704);         // 16384B  [p][col]
    int* tcache = (int*)(sm_raw + 217088);         // 6400B

    const int tid = threadIdx.x;
    const int dir = blockIdx.x >> 6;
    const int b0  = (blockIdx.x & 63) * 8;
    const int j = tid;
    const float* Ug   = dir ? Ub : Uf;
    const float* proj = g_proj[dir];
    float* hout = g_h[dir];

    for (int idx = tid; idx < 96 * GG; idx += 512) Usm[idx] = Ug[idx];
    float ur[32];
    #pragma unroll
    for (int i = 0; i < 32; i++) ur[i] = Ug[(96 + i) * GG + j];

    for (int idx = tid; idx < 8 * TT; idx += 512) {
        int r = idx / TT, t = idx % TT;
        tcache[idx] = tokens[(b0 + r) * TT + t];
    }
    hpack[tid & 511] = 0ULL;   // 512 entries exactly
    __syncthreads();

    float xn[8];
    {
        int t0 = dir ? (TT - 1) : 0;
        #pragma unroll
        for (int r = 0; r < 8; r++)
            xn[r] = proj[(size_t)tcache[r * TT + t0] * GG + j];
    }

    const int m = tid & 127;    // hidden unit in epilogue
    const int p = tid >> 7;     // row-pair in epilogue
    float c0 = 0.0f, c1 = 0.0f; // cell state for rows 2p, 2p+1

    for (int s = 0; s < TT; s++) {
        const int t = dir ? (TT - 1 - s) : s;

        u64 a0 = pk2(xn[0], xn[1]);
        u64 a1 = pk2(xn[2], xn[3]);
        u64 a2 = pk2(xn[4], xn[5]);
        u64 a3 = pk2(xn[6], xn[7]);

        // prefetch next step's xz (hidden under the matmul)
        {
            int sn = (s + 1 < TT) ? (s + 1) : s;
            int tn = dir ? (TT - 1 - sn) : sn;
            #pragma unroll
            for (int r = 0; r < 8; r++)
                xn[r] = proj[(size_t)tcache[r * TT + tn] * GG + j];
        }

        // h @ U : smem rows 0..95
        #pragma unroll 8
        for (int k = 0; k < 96; k += 2) {
            ulonglong2 h0 = *(const ulonglong2*)&hpack[k];
            ulonglong2 h1 = *(const ulonglong2*)&hpack[128 + k];
            ulonglong2 h2 = *(const ulonglong2*)&hpack[256 + k];
            ulonglong2 h3 = *(const ulonglong2*)&hpack[384 + k];
            u64 d0 = dup2(Usm[k * GG + j]);
            u64 d1 = dup2(Usm[(k + 1) * GG + j]);
            a0 = fma2(h0.x, d0, a0); a0 = fma2(h0.y, d1, a0);
            a1 = fma2(h1.x, d0, a1); a1 = fma2(h1.y, d1, a1);
            a2 = fma2(h2.x, d0, a2); a2 = fma2(h2.y, d1, a2);
            a3 = fma2(h3.x, d0, a3); a3 = fma2(h3.y, d1, a3);
        }
        // register rows 96..127
        #pragma unroll
        for (int kk = 0; kk < 32; kk += 2) {
            const int k = 96 + kk;
            ulonglong2 h0 = *(const ulonglong2*)&hpack[k];
            ulonglong2 h1 = *(const ulonglong2*)&hpack[128 + k];
            ulonglong2 h2 = *(const ulonglong2*)&hpack[256 + k];
            ulonglong2 h3 = *(const ulonglong2*)&hpack[384 + k];
            u64 d0 = dup2(ur[kk]);
            u64 d1 = dup2(ur[kk + 1]);
            a0 = fma2(h0.x, d0, a0); a0 = fma2(h0.y, d1, a0);
            a1 = fma2(h1.x, d0, a1); a1 = fma2(h1.y, d1, a1);
            a2 = fma2(h2.x, d0, a2); a2 = fma2(h2.y, d1, a2);
            a3 = fma2(h3.x, d0, a3); a3 = fma2(h3.y, d1, a3);
        }

        // publish z, pair-major: zex[p][col]
        zex[0 * GG + j] = a0;
        zex[1 * GG + j] = a1;
        zex[2 * GG + j] = a2;
        zex[3 * GG + j] = a3;
        __syncthreads();

        // gate epilogue: thread (m, p) handles rows 2p, 2p+1 of hidden m
        {
            u64 vi = zex[p * GG + m];
            u64 vf = zex[p * GG + 128 + m];
            u64 vg = zex[p * GG + 256 + m];
            u64 vo = zex[p * GG + 384 + m];
            float zi0, zi1, zf0, zf1, zg0, zg1, zo0, zo1;
            upk2(vi, zi0, zi1);
            upk2(vf, zf0, zf1);
            upk2(vg, zg0, zg1);
            upk2(vo, zo0, zo1);

            float i0 = sigf(zi0), f0 = sigf(zf0), g0 = fmaxf(zg0, 0.0f), o0 = sigf(zo0);
            float i1 = sigf(zi1), f1 = sigf(zf1), g1 = fmaxf(zg1, 0.0f), o1 = sigf(zo1);
            c0 = f0 * c0 + i0 * g0;
            c1 = f1 * c1 + i1 * g1;
            float h0 = o0 * fmaxf(c0, 0.0f);
            float h1 = o1 * fmaxf(c1, 0.0f);

            hout[((size_t)(b0 + 2 * p)     * TT + t) * HID + m] = h0;
            hout[((size_t)(b0 + 2 * p + 1) * TT + t) * HID + m] = h1;
            hpack[p * 128 + m] = pk2(h0, h1);
        }
        __syncthreads();
    }
}

// ---------------------------------------------------------------------------
// BN + dense(256->9) + softmax. One warp per (b,t). block 256 = 8 positions.
// ---------------------------------------------------------------------------
__global__ __launch_bounds__(256, 4)
void head_kernel(const float* __restrict__ gamma, const float* __restrict__ beta,
                 const float* __restrict__ mean,  const float* __restrict__ var,
                 const float* __restrict__ Wd,    const float* __restrict__ bd,
                 float* __restrict__ out)
{
    __shared__ float scale[2 * HID], shift[2 * HID];
    __shared__ float Wsm[2 * HID * NCLS];
    __shared__ float bsm[NCLS];

    const int tid = threadIdx.x;
    {
        int d = tid;
        float rs = rsqrtf(var[d] + 1e-3f);
        float sc = rs * gamma[d];
        scale[d] = sc;
        shift[d] = beta[d] - mean[d] * sc;
        #pragma unroll
        for (int c = 0; c < NCLS; c++) Wsm[d * NCLS + c] = Wd[d * NCLS + c];
        if (tid < NCLS) bsm[tid] = bd[tid];
    }
    __syncthreads();

    const int wid  = tid >> 5;
    const int lane = tid & 31;
    const int pos  = blockIdx.x * 8 + wid;
    const int d0 = lane * 4;
    const int d1 = 128 + lane * 4;

    float4 hf = *(const float4*)&g_h[0][(size_t)pos * HID + d0];
    float4 hb = *(const float4*)&g_h[1][(size_t)pos * HID + d0];
    float v[8];
    v[0] = hf.x * scale[d0]     + shift[d0];
    v[1] = hf.y * scale[d0 + 1] + shift[d0 + 1];
    v[2] = hf.z * scale[d0 + 2] + shift[d0 + 2];
    v[3] = hf.w * scale[d0 + 3] + shift[d0 + 3];
    v[4] = hb.x * scale[d1]     + shift[d1];
    v[5] = hb.y * scale[d1 + 1] + shift[d1 + 1];
    v[6] = hb.z * scale[d1 + 2] + shift[d1 + 2];
    v[7] = hb.w * scale[d1 + 3] + shift[d1 + 3];

    float acc[NCLS];
    #pragma unroll
    for (int c = 0; c < NCLS; c++) acc[c] = 0.0f;
    #pragma unroll
    for (int i = 0; i < 8; i++) {
        int d = (i < 4) ? (d0 + i) : (d1 + i - 4);
        #pragma unroll
        for (int c = 0; c < NCLS; c++) acc[c] += v[i] * Wsm[d * NCLS + c];
    }
    #pragma unroll
    for (int off = 16; off >= 1; off >>= 1) {
        #pragma unroll
        for (int c = 0; c < NCLS; c++)
            acc[c] += __shfl_xor_sync(0xFFFFFFFFu, acc[c], off);
    }

    if (lane == 0) {
        float z[NCLS], mx = -1e30f;
        #pragma unroll
        for (int c = 0; c < NCLS; c++) { z[c] = acc[c] + bsm[c]; mx = fmaxf(mx, z[c]); }
        float sum = 0.0f;
        #pragma unroll
        for (int c = 0; c < NCLS; c++) { z[c] = __expf(z[c] - mx); sum += z[c]; }
        float inv = __fdividef(1.0f, sum);
        #pragma unroll
        for (int c = 0; c < NCLS; c++) out[(size_t)pos * NCLS + c] = z[c] * inv;
    }
}

extern "C" void kernel_launch(void* const* d_in, const int* in_sizes, int n_in,
                              void* d_out, int out_size)
{
    const int*   tokens = (const int*)d_in[0];
    const float* emb    = (const float*)d_in[1];
    const float* Wf     = (const float*)d_in[2];
    const float* Uf     = (const float*)d_in[3];
    const float* bf     = (const float*)d_in[4];
    const float* Wb     = (const float*)d_in[5];
    const float* Ub     = (const float*)d_in[6];
    const float* bb     = (const float*)d_in[7];
    const float* gamma  = (const float*)d_in[8];
    const float* beta   = (const float*)d_in[9];
    const float* mmean  = (const float*)d_in[10];
    const float* mvar   = (const float*)d_in[11];
    const float* Wd     = (const float*)d_in[12];
    const float* bd     = (const float*)d_in[13];
    float* out = (float*)d_out;

    static bool attr_done = false;
    if (!attr_done) {
        cudaFuncSetAttribute(proj_kernel, cudaFuncAttributeMaxDynamicSharedMemorySize, 211200);
        cudaFuncSetAttribute(lstm_kernel, cudaFuncAttributeMaxDynamicSharedMemorySize, 223488);
        attr_done = true;
    }

    proj_kernel<<<148, 512, 211200>>>(emb, Wf, bf, Wb, bb);
    lstm_kernel<<<128, 512, 223488>>>(tokens, Uf, Ub);
    head_kernel<<<BSZ * TT / 8, 256>>>(gamma, beta, mmean, mvar, Wd, bd, out);
}

// round 4
// speedup vs baseline: 1.2753x; 1.2753x over previous
#include <cuda_runtime.h>
#include <cuda_bf16.h>

#define BSZ   512
#define TT    200
#define HID   128
#define GG    512
#define EMBD  100
#define VOC   30000
#define NCLS  9

// g_proj layout: per dir, float[VOC][256][2] where [v][j][0]=col j, [v][j][1]=col j+256
__device__ float g_proj[2][VOC * GG];
__device__ float g_h[2][BSZ * TT * HID];

typedef unsigned long long u64;

__device__ __forceinline__ u64 pk2(float lo, float hi) {
    u64 r; asm("mov.b64 %0, {%1,%2};" : "=l"(r) : "f"(lo), "f"(hi)); return r;
}
__device__ __forceinline__ void upk2(u64 v, float& lo, float& hi) {
    asm("mov.b64 {%0,%1}, %2;" : "=f"(lo), "=f"(hi) : "l"(v));
}
__device__ __forceinline__ u64 dup2(float x) { return pk2(x, x); }
__device__ __forceinline__ u64 fma2(u64 a, u64 b, u64 c) {
    u64 d; asm("fma.rn.f32x2 %0, %1, %2, %3;" : "=l"(d) : "l"(a), "l"(b), "l"(c)); return d;
}
__device__ __forceinline__ float sigf(float x) {
    return __fdividef(1.0f, 1.0f + __expf(-x));
}

// ---------------------------------------------------------------------------
// proj: register-blocked GEMM. CTA tile = 128 vocab rows x 128 cols, k=100.
// block 256 = 16x16 threads, thread tile 8 rows (4 pairs) x 8 cols.
// grid = 235 row tiles x 4 col tiles x 2 dirs = 1880. 2 CTAs/SM.
// smem: Wt[100][128] f32 (51200B) + ep[100][64] f32x2 (51200B)
// Output layout: float[v][256][2]: faddr = v*512 + (col&255)*2 + (col>>8)
// ---------------------------------------------------------------------------
__global__ __launch_bounds__(256, 2)
void proj_kernel(const float* __restrict__ emb,
                 const float* __restrict__ Wf, const float* __restrict__ bf,
                 const float* __restrict__ Wb, const float* __restrict__ bb)
{
    extern __shared__ char sm_raw[];
    float* Wt = (float*)sm_raw;               // [k][128]
    u64* ep   = (u64*)(sm_raw + 51200);       // [k][64] row-pairs

    const int tid = threadIdx.x;
    const int tx = tid & 15;       // col group
    const int ty = tid >> 4;       // row group
    const int bid = blockIdx.x;
    const int dir = bid & 1;
    const int ct  = (bid >> 1) & 3;
    const int rt  = bid >> 3;
    const int colBase = ct * 128;
    const int rowBase = rt * 128;

    const float* W    = dir ? Wb : Wf;
    const float* bias = dir ? bb : bf;
    float* out = g_proj[dir];

    for (int idx = tid; idx < 100 * 128; idx += 256) {
        int k = idx >> 7, c = idx & 127;
        Wt[idx] = W[k * GG + colBase + c];
    }
    for (int idx = tid; idx < 100 * 64; idx += 256) {
        int p = idx / 100, k = idx - p * 100;
        int ra = rowBase + 2 * p, rb = ra + 1;
        float ea = (ra < VOC) ? emb[ra * EMBD + k] : 0.0f;
        float eb = (rb < VOC) ? emb[rb * EMBD + k] : 0.0f;
        ep[k * 64 + p] = pk2(ea, eb);
    }
    __syncthreads();

    u64 acc[4][8];
    {
        float bj[8];
        #pragma unroll
        for (int c = 0; c < 8; c++) bj[c] = bias[colBase + tx * 8 + c];
        #pragma unroll
        for (int p = 0; p < 4; p++)
            #pragma unroll
            for (int c = 0; c < 8; c++) acc[p][c] = dup2(bj[c]);
    }

    #pragma unroll 4
    for (int k = 0; k < 100; k++) {
        float4 w0 = *(const float4*)&Wt[k * 128 + tx * 8];
        float4 w1 = *(const float4*)&Wt[k * 128 + tx * 8 + 4];
        ulonglong2 e0 = *(const ulonglong2*)&ep[k * 64 + ty * 4];
        ulonglong2 e1 = *(const ulonglong2*)&ep[k * 64 + ty * 4 + 2];
        u64 hp[4] = {e0.x, e0.y, e1.x, e1.y};
        u64 wd[8];
        wd[0] = dup2(w0.x); wd[1] = dup2(w0.y); wd[2] = dup2(w0.z); wd[3] = dup2(w0.w);
        wd[4] = dup2(w1.x); wd[5] = dup2(w1.y); wd[6] = dup2(w1.z); wd[7] = dup2(w1.w);
        #pragma unroll
        for (int p = 0; p < 4; p++)
            #pragma unroll
            for (int c = 0; c < 8; c++)
                acc[p][c] = fma2(hp[p], wd[c], acc[p][c]);
    }

    #pragma unroll
    for (int p = 0; p < 4; p++) {
        int ra = rowBase + ty * 8 + 2 * p;
        int rb = ra + 1;
        #pragma unroll
        for (int c = 0; c < 8; c++) {
            int col = colBase + tx * 8 + c;
            int fo = ((col & 255) << 1) | (col >> 8);
            float oa, ob;
            upk2(acc[p][c], oa, ob);
            if (ra < VOC) out[(size_t)ra * GG + fo] = oa;
            if (rb < VOC) out[(size_t)rb * GG + fo] = ob;
        }
    }
}

// ---------------------------------------------------------------------------
// Persistent recurrent LSTM. grid 128 = 2 dirs x 64 chunks of 8 batch rows.
// block 256; thread owns gate columns j0=tid, j1=tid+256, 4 batch row-pairs.
// smem: Upk[24][512] float4 (U rows 0..95, k-packed) | hpack[4][128] f32x2
//       | zex[4][512] f32x2 | tcache[8][200] int
// ---------------------------------------------------------------------------
__global__ __launch_bounds__(256, 1)
void lstm_kernel(const int* __restrict__ tokens,
                 const float* __restrict__ Uf, const float* __restrict__ Ub)
{
    extern __shared__ char sm_raw[];
    float4* Upk = (float4*)sm_raw;                 // 196608B: [q][j], q=k/4
    u64* hpack  = (u64*)(sm_raw + 196608);         // 4096B: [pair][k]
    u64* zex    = (u64*)(sm_raw + 200704);         // 16384B: [pair][col]
    int* tcache = (int*)(sm_raw + 217088);         // 6400B

    const int tid = threadIdx.x;
    const int dir = blockIdx.x >> 6;
    const int b0  = (blockIdx.x & 63) * 8;
    const int j0 = tid, j1 = tid + 256;
    const float* Ug = dir ? Ub : Uf;
    const u64* proju = (const u64*)g_proj[dir];    // [v][256] pairs
    float* hout = g_h[dir];

    // U rows 0..95 packed into smem as float4 per column
    for (int idx = tid; idx < 24 * GG; idx += 256) {
        int q = idx >> 9, j = idx & 511;
        float4 v;
        v.x = Ug[(4 * q)     * GG + j];
        v.y = Ug[(4 * q + 1) * GG + j];
        v.z = Ug[(4 * q + 2) * GG + j];
        v.w = Ug[(4 * q + 3) * GG + j];
        Upk[idx] = v;
    }
    // U rows 96..127 in registers
    float ur0[32], ur1[32];
    #pragma unroll
    for (int i = 0; i < 32; i++) {
        ur0[i] = Ug[(96 + i) * GG + j0];
        ur1[i] = Ug[(96 + i) * GG + j1];
    }
    for (int idx = tid; idx < 8 * TT; idx += 256) {
        int r = idx / TT, t = idx % TT;
        tcache[idx] = tokens[(b0 + r) * TT + t];
    }
    hpack[tid] = 0ULL;
    hpack[tid + 256] = 0ULL;
    __syncthreads();

    u64 xn[8];
    {
        int t0 = dir ? (TT - 1) : 0;
        #pragma unroll
        for (int r = 0; r < 8; r++)
            xn[r] = proju[(size_t)tcache[r * TT + t0] * 256 + tid];
    }

    const int m  = tid >> 1;        // hidden unit in epilogue
    const int pb = (tid & 1) * 2;   // first row-pair in epilogue
    float cst[4] = {0.f, 0.f, 0.f, 0.f};

    for (int s = 0; s < TT; s++) {
        const int t = dir ? (TT - 1 - s) : s;

        // unpack prefetched xz pairs into accumulators
        u64 a0, a1, a2, a3, a10, a11, a12, a13;
        {
            float l0,h0,l1,h1,l2,h2,l3,h3,l4,h4,l5,h5,l6,h6,l7,h7;
            upk2(xn[0], l0, h0); upk2(xn[1], l1, h1);
            upk2(xn[2], l2, h2); upk2(xn[3], l3, h3);
            upk2(xn[4], l4, h4); upk2(xn[5], l5, h5);
            upk2(xn[6], l6, h6); upk2(xn[7], l7, h7);
            a0  = pk2(l0, l1); a1  = pk2(l2, l3); a2  = pk2(l4, l5); a3  = pk2(l6, l7);
            a10 = pk2(h0, h1); a11 = pk2(h2, h3); a12 = pk2(h4, h5); a13 = pk2(h6, h7);
        }

        // prefetch next step's xz (hidden under the matmul)
        {
            int sn = (s + 1 < TT) ? (s + 1) : s;
            int tn = dir ? (TT - 1 - sn) : sn;
            #pragma unroll
            for (int r = 0; r < 8; r++)
                xn[r] = proju[(size_t)tcache[r * TT + tn] * 256 + tid];
        }

        // h @ U, smem rows 0..95 in 4-k groups
        #pragma unroll 4
        for (int q = 0; q < 24; q++) {
            float4 u0 = Upk[q * GG + j0];
            float4 u1 = Upk[q * GG + j1];
            const int k = 4 * q;
            ulonglong2 hA = *(const ulonglong2*)&hpack[k];
            ulonglong2 hA2= *(const ulonglong2*)&hpack[k + 2];
            ulonglong2 hB = *(const ulonglong2*)&hpack[128 + k];
            ulonglong2 hB2= *(const ulonglong2*)&hpack[128 + k + 2];
            ulonglong2 hC = *(const ulonglong2*)&hpack[256 + k];
            ulonglong2 hC2= *(const ulonglong2*)&hpack[256 + k + 2];
            ulonglong2 hD = *(const ulonglong2*)&hpack[384 + k];
            ulonglong2 hD2= *(const ulonglong2*)&hpack[384 + k + 2];
            u64 w00 = dup2(u0.x), w01 = dup2(u0.y), w02 = dup2(u0.z), w03 = dup2(u0.w);
            u64 w10 = dup2(u1.x), w11 = dup2(u1.y), w12 = dup2(u1.z), w13 = dup2(u1.w);
            a0  = fma2(hA.x,  w00, a0);  a0  = fma2(hA.y,  w01, a0);
            a0  = fma2(hA2.x, w02, a0);  a0  = fma2(hA2.y, w03, a0);
            a1  = fma2(hB.x,  w00, a1);  a1  = fma2(hB.y,  w01, a1);
            a1  = fma2(hB2.x, w02, a1);  a1  = fma2(hB2.y, w03, a1);
            a2  = fma2(hC.x,  w00, a2);  a2  = fma2(hC.y,  w01, a2);
            a2  = fma2(hC2.x, w02, a2);  a2  = fma2(hC2.y, w03, a2);
            a3  = fma2(hD.x,  w00, a3);  a3  = fma2(hD.y,  w01, a3);
            a3  = fma2(hD2.x, w02, a3);  a3  = fma2(hD2.y, w03, a3);
            a10 = fma2(hA.x,  w10, a10); a10 = fma2(hA.y,  w11, a10);
            a10 = fma2(hA2.x, w12, a10); a10 = fma2(hA2.y, w13, a10);
            a11 = fma2(hB.x,  w10, a11); a11 = fma2(hB.y,  w11, a11);
            a11 = fma2(hB2.x, w12, a11); a11 = fma2(hB2.y, w13, a11);
            a12 = fma2(hC.x,  w10, a12); a12 = fma2(hC.y,  w11, a12);
            a12 = fma2(hC2.x, w12, a12); a12 = fma2(hC2.y, w13, a12);
            a13 = fma2(hD.x,  w10, a13); a13 = fma2(hD.y,  w11, a13);
            a13 = fma2(hD2.x, w12, a13); a13 = fma2(hD2.y, w13, a13);
        }
        // register rows 96..127
        #pragma unroll
        for (int qq = 0; qq < 8; qq++) {
            const int k = 96 + 4 * qq;
            ulonglong2 hA = *(const ulonglong2*)&hpack[k];
            ulonglong2 hA2= *(const ulonglong2*)&hpack[k + 2];
            ulonglong2 hB = *(const ulonglong2*)&hpack[128 + k];
            ulonglong2 hB2= *(const ulonglong2*)&hpack[128 + k + 2];
            ulonglong2 hC = *(const ulonglong2*)&hpack[256 + k];
            ulonglong2 hC2= *(const ulonglong2*)&hpack[256 + k + 2];
            ulonglong2 hD = *(const ulonglong2*)&hpack[384 + k];
            ulonglong2 hD2= *(const ulonglong2*)&hpack[384 + k + 2];
            u64 w00 = dup2(ur0[4*qq]), w01 = dup2(ur0[4*qq+1]);
            u64 w02 = dup2(ur0[4*qq+2]), w03 = dup2(ur0[4*qq+3]);
            u64 w10 = dup2(ur1[4*qq]), w11 = dup2(ur1[4*qq+1]);
            u64 w12 = dup2(ur1[4*qq+2]), w13 = dup2(ur1[4*qq+3]);
            a0  = fma2(hA.x,  w00, a0);  a0  = fma2(hA.y,  w01, a0);
            a0  = fma2(hA2.x, w02, a0);  a0  = fma2(hA2.y, w03, a0);
            a1  = fma2(hB.x,  w00, a1);  a1  = fma2(hB.y,  w01, a1);
            a1  = fma2(hB2.x, w02, a1);  a1  = fma2(hB2.y, w03, a1);
            a2  = fma2(hC.x,  w00, a2);  a2  = fma2(hC.y,  w01, a2);
            a2  = fma2(hC2.x, w02, a2);  a2  = fma2(hC2.y, w03, a2);
            a3  = fma2(hD.x,  w00, a3);  a3  = fma2(hD.y,  w01, a3);
            a3  = fma2(hD2.x, w02, a3);  a3  = fma2(hD2.y, w03, a3);
            a10 = fma2(hA.x,  w10, a10); a10 = fma2(hA.y,  w11, a10);
            a10 = fma2(hA2.x, w12, a10); a10 = fma2(hA2.y, w13, a10);
            a11 = fma2(hB.x,  w10, a11); a11 = fma2(hB.y,  w11, a11);
            a11 = fma2(hB2.x, w12, a11); a11 = fma2(hB2.y, w13, a11);
            a12 = fma2(hC.x,  w10, a12); a12 = fma2(hC.y,  w11, a12);
            a12 = fma2(hC2.x, w12, a12); a12 = fma2(hC2.y, w13, a12);
            a13 = fma2(hD.x,  w10, a13); a13 = fma2(hD.y,  w11, a13);
            a13 = fma2(hD2.x, w12, a13); a13 = fma2(hD2.y, w13, a13);
        }

        // publish z: zex[pair][col]
        zex[0 * GG + j0] = a0;  zex[1 * GG + j0] = a1;
        zex[2 * GG + j0] = a2;  zex[3 * GG + j0] = a3;
        zex[0 * GG + j1] = a10; zex[1 * GG + j1] = a11;
        zex[2 * GG + j1] = a12; zex[3 * GG + j1] = a13;
        __syncthreads();

        // gate epilogue: thread (m, pb) handles rows 2pb..2pb+3 of hidden m
        {
            u64 vi0 = zex[pb * GG + m],             vi1 = zex[(pb + 1) * GG + m];
            u64 vf0 = zex[pb * GG + 128 + m],       vf1 = zex[(pb + 1) * GG + 128 + m];
            u64 vg0 = zex[pb * GG + 256 + m],       vg1 = zex[(pb + 1) * GG + 256 + m];
            u64 vo0 = zex[pb * GG + 384 + m],       vo1 = zex[(pb + 1) * GG + 384 + m];
            float zi[4], zf[4], zg[4], zo[4], hv[4];
            upk2(vi0, zi[0], zi[1]); upk2(vi1, zi[2], zi[3]);
            upk2(vf0, zf[0], zf[1]); upk2(vf1, zf[2], zf[3]);
            upk2(vg0, zg[0], zg[1]); upk2(vg1, zg[2], zg[3]);
            upk2(vo0, zo[0], zo[1]); upk2(vo1, zo[2], zo[3]);
            #pragma unroll
            for (int r = 0; r < 4; r++) {
                float ii = sigf(zi[r]);
                float ff = sigf(zf[r]);
                float gg = fmaxf(zg[r], 0.0f);
                float oo = sigf(zo[r]);
                float c  = ff * cst[r] + ii * gg;
                cst[r] = c;
                hv[r] = oo * fmaxf(c, 0.0f);
                hout[((size_t)(b0 + 2 * pb + r) * TT + t) * HID + m] = hv[r];
            }
            hpack[pb * 128 + m]       = pk2(hv[0], hv[1]);
            hpack[(pb + 1) * 128 + m] = pk2(hv[2], hv[3]);
        }
        __syncthreads();
    }
}

// ---------------------------------------------------------------------------
// BN + dense(256->9) + softmax. One warp per (b,t). block 256 = 8 positions.
// ---------------------------------------------------------------------------
__global__ __launch_bounds__(256, 4)
void head_kernel(const float* __restrict__ gamma, const float* __restrict__ beta,
                 const float* __restrict__ mean,  const float* __restrict__ var,
                 const float* __restrict__ Wd,    const float* __restrict__ bd,
                 float* __restrict__ out)
{
    __shared__ float scale[2 * HID], shift[2 * HID];
    __shared__ float Wsm[2 * HID * NCLS];
    __shared__ float bsm[NCLS];

    const int tid = threadIdx.x;
    {
        int d = tid;
        float rs = rsqrtf(var[d] + 1e-3f);
        float sc = rs * gamma[d];
        scale[d] = sc;
        shift[d] = beta[d] - mean[d] * sc;
        #pragma unroll
        for (int c = 0; c < NCLS; c++) Wsm[d * NCLS + c] = Wd[d * NCLS + c];
        if (tid < NCLS) bsm[tid] = bd[tid];
    }
    __syncthreads();

    const int wid  = tid >> 5;
    const int lane = tid & 31;
    const int pos  = blockIdx.x * 8 + wid;
    const int d0 = lane * 4;
    const int d1 = 128 + lane * 4;

    float4 hf = *(const float4*)&g_h[0][(size_t)pos * HID + d0];
    float4 hb = *(const float4*)&g_h[1][(size_t)pos * HID + d0];
    float v[8];
    v[0] = hf.x * scale[d0]     + shift[d0];
    v[1] = hf.y * scale[d0 + 1] + shift[d0 + 1];
    v[2] = hf.z * scale[d0 + 2] + shift[d0 + 2];
    v[3] = hf.w * scale[d0 + 3] + shift[d0 + 3];
    v[4] = hb.x * scale[d1]     + shift[d1];
    v[5] = hb.y * scale[d1 + 1] + shift[d1 + 1];
    v[6] = hb.z * scale[d1 + 2] + shift[d1 + 2];
    v[7] = hb.w * scale[d1 + 3] + shift[d1 + 3];

    float acc[NCLS];
    #pragma unroll
    for (int c = 0; c < NCLS; c++) acc[c] = 0.0f;
    #pragma unroll
    for (int i = 0; i < 8; i++) {
        int d = (i < 4) ? (d0 + i) : (d1 + i - 4);
        #pragma unroll
        for (int c = 0; c < NCLS; c++) acc[c] += v[i] * Wsm[d * NCLS + c];
    }
    #pragma unroll
    for (int off = 16; off >= 1; off >>= 1) {
        #pragma unroll
        for (int c = 0; c < NCLS; c++)
            acc[c] += __shfl_xor_sync(0xFFFFFFFFu, acc[c], off);
    }

    if (lane == 0) {
        float z[NCLS], mx = -1e30f;
        #pragma unroll
        for (int c = 0; c < NCLS; c++) { z[c] = acc[c] + bsm[c]; mx = fmaxf(mx, z[c]); }
        float sum = 0.0f;
        #pragma unroll
        for (int c = 0; c < NCLS; c++) { z[c] = __expf(z[c] - mx); sum += z[c]; }
        float inv = __fdividef(1.0f, sum);
        #pragma unroll
        for (int c = 0; c < NCLS; c++) out[(size_t)pos * NCLS + c] = z[c] * inv;
    }
}

extern "C" void kernel_launch(void* const* d_in, const int* in_sizes, int n_in,
                              void* d_out, int out_size)
{
    const int*   tokens = (const int*)d_in[0];
    const float* emb    = (const float*)d_in[1];
    const float* Wf     = (const float*)d_in[2];
    const float* Uf     = (const float*)d_in[3];
    const float* bf     = (const float*)d_in[4];
    const float* Wb     = (const float*)d_in[5];
    const float* Ub     = (const float*)d_in[6];
    const float* bb     = (const float*)d_in[7];
    const float* gamma  = (const float*)d_in[8];
    const float* beta   = (const float*)d_in[9];
    const float* mmean  = (const float*)d_in[10];
    const float* mvar   = (const float*)d_in[11];
    const float* Wd     = (const float*)d_in[12];
    const float* bd     = (const float*)d_in[13];
    float* out = (float*)d_out;

    static bool attr_done = false;
    if (!attr_done) {
        cudaFuncSetAttribute(proj_kernel, cudaFuncAttributeMaxDynamicSharedMemorySize, 102400);
        cudaFuncSetAttribute(lstm_kernel, cudaFuncAttributeMaxDynamicSharedMemorySize, 223488);
        attr_done = true;
    }

    proj_kernel<<<235 * 4 * 2, 256, 102400>>>(emb, Wf, bf, Wb, bb);
    lstm_kernel<<<128, 256, 223488>>>(tokens, Uf, Ub);
    head_kernel<<<BSZ * TT / 8, 256>>>(gamma, beta, mmean, mvar, Wd, bd, out);
}